// round 15
// baseline (speedup 1.0000x reference)
#include <cuda_runtime.h>
#include <math.h>

#define SEQ 2048
#define DMODEL 1024
#define QH 16
#define KVH 4
#define DH 64
#define TOPK 64
#define CCAP 256

// ---------------- scratch (__device__ globals; no allocations) ----------------
__device__ float2 g_Qff[SEQ * QH * DH];            // 16 MB roped q, float-float
__device__ float2 g_Kff[SEQ * KVH * DH];           // 4 MB  roped k, float-float
__device__ float g_Qh32[SEQ * QH * DH];            // 4 MB  hi copy for plain score GEMM
__device__ float g_Kh32[SEQ * KVH * DH];           // 1 MB
__device__ float g_V[SEQ * KVH * DH];              // 2 MB
__device__ float g_AO[SEQ * QH * DH];              // 8 MB
__device__ float g_S[QH * (size_t)SEQ * SEQ];      // 256 MB approx score slab per head
__device__ float g_cos[SEQ * 32];
__device__ float g_sin[SEQ * 32];

// ---------------- float-float primitives ----------------
// TwoSum variant (6-op compensation). PROVEN REQUIRED: Fast2Sum (round 14)
// raised rel_err 9.18e-4 -> 1.18e-3 via dropped low parts at near-zero
// accumulator crossings. Do not weaken this again.
__device__ __forceinline__ void ff_mac(float& h, float& l, float a, float b) {
    float p = a * b;
    float e = fmaf(a, b, -p);       // exact product error
    float s = h + p;
    float bb = s - h;
    float err = (h - (s - bb)) + (p - bb);
    h = s;
    l += err + e;
}

// ---------------- RoPE table: bit-match the reference's f32 op chain ----------------
__global__ void rope_table_kernel() {
    int idx = blockIdx.x * blockDim.x + threadIdx.x;
    if (idx >= SEQ * 32) return;
    int i = idx & 31;
    int pos = idx >> 5;
    float p32 = (float)pow(10000.0, (double)i / 32.0);
    float invf = 1.0f / p32;
    float ang = (float)pos * invf;
    const double TWO_PI = 6.283185307179586476925286766559;
    double dr = (double)ang;
    dr -= TWO_PI * floor(dr / TWO_PI + 0.5);
    g_cos[idx] = (float)cos(dr);
    g_sin[idx] = (float)sin(dr);
}

// ---------------- tiled NT GEMM -> float-float output (Q,K projections) ----------------
__global__ __launch_bounds__(256) void gemm_nt_ff(const float* __restrict__ A,
                                                  const float* __restrict__ B,
                                                  float2* __restrict__ C,
                                                  int M, int N, int K) {
    __shared__ float As[16][68];
    __shared__ float Bs[16][68];
    int bm = blockIdx.y * 64, bn = blockIdx.x * 64;
    int tid = threadIdx.x;
    int tx = tid & 15, ty = tid >> 4;
    float ah[4][4] = {}, al[4][4] = {};
    for (int k0 = 0; k0 < K; k0 += 16) {
#pragma unroll
        for (int t = 0; t < 4; t++) {
            int idx = tid + t * 256;
            int r = idx >> 4, kk = idx & 15;
            As[kk][r] = A[(size_t)(bm + r) * K + k0 + kk];
            Bs[kk][r] = B[(size_t)(bn + r) * K + k0 + kk];
        }
        __syncthreads();
#pragma unroll
        for (int kk = 0; kk < 16; kk++) {
            // contiguous + 16B-aligned (row stride 272B, offset ty*16B) -> LDS.128
            float4 av = *(const float4*)&As[kk][ty * 4];
            float4 bv = *(const float4*)&Bs[kk][tx * 4];
            float a[4] = {av.x, av.y, av.z, av.w};
            float b[4] = {bv.x, bv.y, bv.z, bv.w};
#pragma unroll
            for (int i = 0; i < 4; i++)
#pragma unroll
                for (int j = 0; j < 4; j++) ff_mac(ah[i][j], al[i][j], a[i], b[j]);
        }
        __syncthreads();
    }
#pragma unroll
    for (int i = 0; i < 4; i++)
#pragma unroll
        for (int j = 0; j < 4; j++) {
            float hh = ah[i][j] + al[i][j];               // renormalize
            float ll = al[i][j] - (hh - ah[i][j]);
            C[(size_t)(bm + ty * 4 + i) * N + bn + tx * 4 + j] = make_float2(hh, ll);
        }
}

// ---------------- tiled NT GEMM fp32 (V proj, out proj) ----------------
__global__ __launch_bounds__(256) void gemm_nt(const float* __restrict__ A,
                                               const float* __restrict__ B,
                                               float* __restrict__ C,
                                               int M, int N, int K) {
    __shared__ float As[16][68];
    __shared__ float Bs[16][68];
    int bm = blockIdx.y * 64, bn = blockIdx.x * 64;
    int tid = threadIdx.x;
    int tx = tid & 15, ty = tid >> 4;
    float acc[4][4] = {};
    for (int k0 = 0; k0 < K; k0 += 16) {
#pragma unroll
        for (int t = 0; t < 4; t++) {
            int idx = tid + t * 256;
            int r = idx >> 4, kk = idx & 15;
            As[kk][r] = A[(size_t)(bm + r) * K + k0 + kk];
            Bs[kk][r] = B[(size_t)(bn + r) * K + k0 + kk];
        }
        __syncthreads();
#pragma unroll
        for (int kk = 0; kk < 16; kk++) {
            float4 av = *(const float4*)&As[kk][ty * 4];
            float4 bv = *(const float4*)&Bs[kk][tx * 4];
            float a[4] = {av.x, av.y, av.z, av.w};
            float b[4] = {bv.x, bv.y, bv.z, bv.w};
#pragma unroll
            for (int i = 0; i < 4; i++)
#pragma unroll
                for (int j = 0; j < 4; j++) acc[i][j] += a[i] * b[j];
        }
        __syncthreads();
    }
#pragma unroll
    for (int i = 0; i < 4; i++)
#pragma unroll
        for (int j = 0; j < 4; j++)
            C[(size_t)(bm + ty * 4 + i) * N + bn + tx * 4 + j] = acc[i][j];
}

// ---------------- RoPE apply on float-float arrays; also writes hi copy ----------------
__global__ void rope_ff(float2* __restrict__ X, float* __restrict__ Xh, int n_heads) {
    int idx = blockIdx.x * blockDim.x + threadIdx.x;
    int total = SEQ * n_heads * 32;
    if (idx >= total) return;
    int i = idx % 32;
    int h = (idx / 32) % n_heads;
    int pos = idx / (32 * n_heads);
    double c = (double)g_cos[pos * 32 + i];
    double s = (double)g_sin[pos * 32 + i];
    size_t base = (size_t)pos * (n_heads * DH) + h * DH;
    float2* row = X + base;
    double x1 = (double)row[i].x + (double)row[i].y;
    double x2 = (double)row[i + 32].x + (double)row[i + 32].y;
    double r1 = x1 * c - x2 * s;
    double r2 = x2 * c + x1 * s;
    float h1 = (float)r1, h2 = (float)r2;
    row[i]      = make_float2(h1, (float)(r1 - (double)h1));
    row[i + 32] = make_float2(h2, (float)(r2 - (double)h2));
    Xh[base + i] = h1;
    Xh[base + i + 32] = h2;
}

// monotone float->uint map (order-preserving)
__device__ __forceinline__ unsigned fmap(float f) {
    unsigned u = __float_as_uint(f);
    return (u & 0x80000000u) ? ~u : (u | 0x80000000u);
}
// inverse of fmap
__device__ __forceinline__ float funmap(unsigned u) {
    return __uint_as_float((u & 0x80000000u) ? (u & 0x7FFFFFFFu) : ~u);
}

// ---------------- approx score GEMM (plain fp32 on hi parts), 16 heads ----------------
__global__ __launch_bounds__(256) void score_plain16() {
    __shared__ float Qs[64][65];
    __shared__ float Ks[64][65];
    int tid = threadIdx.x;
    int h = blockIdx.y;
    int t = blockIdx.x;
    int bi = (int)((sqrtf(8.0f * (float)t + 1.0f) - 1.0f) * 0.5f);
    while ((bi + 1) * (bi + 2) / 2 <= t) bi++;
    while (bi * (bi + 1) / 2 > t) bi--;
    int bj = t - bi * (bi + 1) / 2;
    int qi0 = bi * 64, j0 = bj * 64;
    int kvh = h >> 2;
    float* Sh = g_S + (size_t)h * SEQ * SEQ;
    const float* Qp = g_Qh32 + (size_t)qi0 * (QH * DH) + h * DH;
    const float* Kp = g_Kh32 + (size_t)j0 * (KVH * DH) + kvh * DH;

#pragma unroll
    for (int p = 0; p < 16; p++) {
        int idx = tid + p * 256;
        int d = idx & 63, r = idx >> 6;
        Qs[d][r] = Qp[(size_t)r * (QH * DH) + d];
        Ks[d][r] = Kp[(size_t)r * (KVH * DH) + d];
    }
    __syncthreads();

    int tx = tid & 15, ty = tid >> 4;
    float acc[4][4] = {};
#pragma unroll 8
    for (int kk = 0; kk < 64; kk++) {
        float a[4], b[4];
#pragma unroll
        for (int i = 0; i < 4; i++) a[i] = Qs[kk][ty + 16 * i];
#pragma unroll
        for (int j = 0; j < 4; j++) b[j] = Ks[kk][tx + 16 * j];
#pragma unroll
        for (int i = 0; i < 4; i++)
#pragma unroll
            for (int j = 0; j < 4; j++) acc[i][j] += a[i] * b[j];
    }
#pragma unroll
    for (int i = 0; i < 4; i++) {
        int qi = qi0 + ty + 16 * i;
#pragma unroll
        for (int j = 0; j < 4; j++) {
            int jj = j0 + tx + 16 * j;
            if (jj <= qi)
                Sh[(size_t)qi * SEQ + jj] = acc[i][j] * 0.125f;
        }
    }
}

// ---------------- attention: parallel radix cutoff -> exact recompute of candidates ----------------
__global__ __launch_bounds__(256) void attn16() {
    __shared__ float sc[SEQ];
    __shared__ int hist[256];
    __shared__ int cidx[CCAP];
    __shared__ float cval[CCAP];
    __shared__ float cwgt[CCAP];
    __shared__ float2 q2s[DH];
    __shared__ float fred[8];
    __shared__ int s_wc[8];
    __shared__ float s_smax, s_den;
    __shared__ int s_b, s_k, s_cnt;
    __shared__ float4 red4[16][16];

    int tid = threadIdx.x, lane = tid & 31, wid = tid >> 5;
    int qi = blockIdx.x;
    int h = blockIdx.y;
    int kvh = h >> 2;
    int len = qi + 1;

    if (tid < DH) q2s[tid] = g_Qff[(size_t)qi * (QH * DH) + h * DH + tid];
    hist[tid] = 0;
    __syncthreads();

    // ---- fused row load + level-1 histogram (bits [31:24]) ----
    const float* Srow = g_S + (size_t)h * SEQ * SEQ + (size_t)qi * SEQ;
    for (int j = tid; j < len; j += 256) {
        float v = Srow[j];
        sc[j] = v;
        atomicAdd(&hist[fmap(v) >> 24], 1);
    }
    __syncthreads();

    float vlo = -INFINITY;
    if (len > TOPK) {
        // ---- level-1: parallel suffix scan, find cutoff bin ----
        {
            int rs = 255 - tid;
            int v1 = hist[rs];
            int x = v1;
#pragma unroll
            for (int o = 1; o < 32; o <<= 1) {
                int y = __shfl_up_sync(0xffffffffu, x, o);
                if (lane >= o) x += y;
            }
            if (lane == 31) s_wc[wid] = x;
            __syncthreads();
            int wo = 0;
            for (int w = 0; w < wid; w++) wo += s_wc[w];
            int incl = x + wo, excl = incl - v1;
            if (incl >= TOPK && excl < TOPK) { s_b = rs; s_k = TOPK - excl; }
            __syncthreads();
        }
        int b1 = s_b, k1 = s_k;

        // ---- level-2 histogram (bits [23:16]) within bin b1 ----
        hist[tid] = 0;
        __syncthreads();
        for (int j = tid; j < len; j += 256) {
            unsigned u = fmap(sc[j]);
            if ((int)(u >> 24) == b1) atomicAdd(&hist[(u >> 16) & 0xFF], 1);
        }
        __syncthreads();
        {
            int rs = 255 - tid;
            int v1 = hist[rs];
            int x = v1;
#pragma unroll
            for (int o = 1; o < 32; o <<= 1) {
                int y = __shfl_up_sync(0xffffffffu, x, o);
                if (lane >= o) x += y;
            }
            if (lane == 31) s_wc[wid] = x;
            __syncthreads();
            int wo = 0;
            for (int w = 0; w < wid; w++) wo += s_wc[w];
            int incl = x + wo, excl = incl - v1;
            if (incl >= k1 && excl < k1) s_b = rs;
            __syncthreads();
        }
        unsigned floorx = ((unsigned)b1 << 24) | ((unsigned)s_b << 16);
        vlo = funmap(floorx);
    }

    // ---- deterministic compaction: per-thread collect + block exclusive scan ----
    int cnt = 0;
    for (int attempt = 0; attempt < 2; attempt++) {
        float cutoff = (len > TOPK) ? (attempt == 0 ? vlo - 1e-4f : vlo) : -INFINITY;
        int lc = 0;
        int lcs[8];
        for (int c = 0; c * 256 + tid < len; c++) {
            int j = c * 256 + tid;
            if (sc[j] >= cutoff) lcs[lc++] = j;
        }
        int x = lc;
#pragma unroll
        for (int o = 1; o < 32; o <<= 1) {
            int y = __shfl_up_sync(0xffffffffu, x, o);
            if (lane >= o) x += y;
        }
        if (lane == 31) s_wc[wid] = x;
        __syncthreads();
        int wo = 0;
        for (int w = 0; w < wid; w++) wo += s_wc[w];
        int off = wo + x - lc;
        if (tid == 0) {
            int t = 0;
            for (int w = 0; w < 8; w++) t += s_wc[w];
            s_cnt = t;
        }
        for (int i = 0; i < lc; i++) {
            int pos = off + i;
            if (pos < CCAP) cidx[pos] = lcs[i];
        }
        __syncthreads();
        cnt = s_cnt < CCAP ? s_cnt : CCAP;
        if (s_cnt <= CCAP || len <= TOPK) break;
        __syncthreads();
    }

    // ---- exact ff recompute for candidates (warp per candidate) ----
    for (int t = wid; t < cnt; t += 8) {
        int j = cidx[t];
        const float2* kr = g_Kff + (size_t)j * (KVH * DH) + kvh * DH;
        float2 k1v = kr[lane], k2v = kr[lane + 32];
        float2 qa = q2s[lane], qb = q2s[lane + 32];
        float sh = 0.f, sl = 0.f;
        ff_mac(sh, sl, qa.x, k1v.x);
        sl += qa.x * k1v.y + qa.y * k1v.x;
        ff_mac(sh, sl, qb.x, k2v.x);
        sl += qb.x * k2v.y + qb.y * k2v.x;
#pragma unroll
        for (int o = 16; o; o >>= 1) {
            float oh = __shfl_xor_sync(0xffffffffu, sh, o);
            float ol = __shfl_xor_sync(0xffffffffu, sl, o);
            float s = sh + oh;
            float bb = s - sh;
            float err = (sh - (s - bb)) + (oh - bb);
            sh = s;
            sl += ol + err;
        }
        if (lane == 0) cval[t] = (sh + sl) * 0.125f;
    }
    __syncthreads();

    // ---- smax over candidate exacts (global max is always a candidate) ----
    {
        float lm = (tid < cnt) ? cval[tid] : -INFINITY;
#pragma unroll
        for (int o = 16; o; o >>= 1) lm = fmaxf(lm, __shfl_xor_sync(0xffffffffu, lm, o));
        if (lane == 0) fred[wid] = lm;
        __syncthreads();
        if (tid == 0) {
            float mm = fred[0];
            for (int w = 1; w < 8; w++) mm = fmaxf(mm, fred[w]);
            s_smax = mm;
        }
        __syncthreads();
    }
    float smax = s_smax;

    // ---- exact 64th-largest among candidates via bit search (deterministic) ----
    unsigned myu = (tid < cnt) ? fmap(cval[tid]) : 0u;
    unsigned thru = 0;
    if (len > TOPK) {
        unsigned prefix = 0;
#pragma unroll
        for (int b = 31; b >= 0; b--) {
            unsigned cand = prefix | (1u << b);
            int c = __syncthreads_count((tid < cnt) && (myu >= cand));
            if (c >= TOPK) prefix = cand;
        }
        thru = prefix;  // exact u of the 64th-largest true score; keep u >= thru (ties kept)
    }

    // ---- weights ----
    {
        float w = 0.f;
        if (tid < cnt && myu >= thru) w = expf(cval[tid] - smax);
        cwgt[tid] = w;
    }
    __syncthreads();

    // ---- denominator (fixed order) ----
    {
        float part = cwgt[tid];
#pragma unroll
        for (int o = 16; o; o >>= 1) part += __shfl_xor_sync(0xffffffffu, part, o);
        if (lane == 0) fred[wid] = part;
        __syncthreads();
        if (tid == 0) {
            float d = 0.f;
            for (int w = 0; w < 8; w++) d += fred[w];
            s_den = d;
        }
        __syncthreads();
    }
    float inv = 1.f / s_den;

    // ---- AV over candidate list: 16 groups x 16 float4-dims ----
    {
        int g = tid >> 4, d4 = tid & 15;
        float4 a = make_float4(0.f, 0.f, 0.f, 0.f);
        for (int t = g; t < cnt; t += 16) {
            float wv = cwgt[t];
            if (wv != 0.f) {
                float4 vv = *((const float4*)(g_V + (size_t)cidx[t] * (KVH * DH) + kvh * DH) + d4);
                a.x += wv * vv.x; a.y += wv * vv.y;
                a.z += wv * vv.z; a.w += wv * vv.w;
            }
        }
        red4[g][d4] = a;
    }
    __syncthreads();
    if (tid < 16) {
        float4 a = make_float4(0.f, 0.f, 0.f, 0.f);
        for (int g = 0; g < 16; g++) {
            float4 v = red4[g][tid];
            a.x += v.x; a.y += v.y; a.z += v.z; a.w += v.w;
        }
        a.x *= inv; a.y *= inv; a.z *= inv; a.w *= inv;
        *((float4*)(g_AO + (size_t)qi * (QH * DH) + h * DH) + tid) = a;
    }
}

// ---------------- launch ----------------
extern "C" void kernel_launch(void* const* d_in, const int* in_sizes, int n_in,
                              void* d_out, int out_size) {
    (void)out_size;
    int ixv = -1, big[2] = {-1, -1}, sml[2] = {-1, -1};
    int nb = 0, ns = 0;
    for (int i = 0; i < n_in; i++) {
        if (in_sizes[i] == SEQ * DMODEL && ixv < 0) ixv = i;
        else if (in_sizes[i] == QH * DH * DMODEL && nb < 2) big[nb++] = i;
        else if (in_sizes[i] == KVH * DH * DMODEL && ns < 2) sml[ns++] = i;
    }
    if (ixv < 0 || nb < 2 || ns < 2) {
        ixv = 0; big[0] = 1; big[1] = 4; sml[0] = 2; sml[1] = 3;
    }
    const float* x  = (const float*)d_in[ixv];
    const float* Wq = (const float*)d_in[big[0]];
    const float* Wo = (const float*)d_in[big[1]];
    const float* Wk = (const float*)d_in[sml[0]];
    const float* Wv = (const float*)d_in[sml[1]];
    float* out = (float*)d_out;

    float2 *Qff, *Kff;
    float *V, *AO, *Qh32, *Kh32;
    cudaGetSymbolAddress((void**)&Qff, g_Qff);
    cudaGetSymbolAddress((void**)&Kff, g_Kff);
    cudaGetSymbolAddress((void**)&V, g_V);
    cudaGetSymbolAddress((void**)&AO, g_AO);
    cudaGetSymbolAddress((void**)&Qh32, g_Qh32);
    cudaGetSymbolAddress((void**)&Kh32, g_Kh32);

    rope_table_kernel<<<(SEQ * 32 + 255) / 256, 256>>>();

    // order keeps gemm_nt_ff(K) in the ncu -s5-c1 capture slot (launch #4):
    // the direct ff-GEMM measurement drives the next optimization decision.
    gemm_nt<<<dim3((KVH * DH) / 64, SEQ / 64), 256>>>(x, Wv, V, SEQ, KVH * DH, DMODEL);
    gemm_nt_ff<<<dim3((QH * DH) / 64, SEQ / 64), 256>>>(x, Wq, Qff, SEQ, QH * DH, DMODEL);
    gemm_nt_ff<<<dim3((KVH * DH) / 64, SEQ / 64), 256>>>(x, Wk, Kff, SEQ, KVH * DH, DMODEL);

    rope_ff<<<(SEQ * QH * 32) / 256, 256>>>(Qff, Qh32, QH);
    rope_ff<<<(SEQ * KVH * 32) / 256, 256>>>(Kff, Kh32, KVH);

    const int NT = (SEQ / 64) * (SEQ / 64 + 1) / 2;  // 528 triangular tiles
    score_plain16<<<dim3(NT, QH), 256>>>();
    attn16<<<dim3(SEQ, QH), 256>>>();

    gemm_nt<<<dim3(DMODEL / 64, SEQ / 64), 256>>>(AO, Wo, out, SEQ, DMODEL, QH * DH);
}

// round 16
// speedup vs baseline: 1.0195x; 1.0195x over previous
#include <cuda_runtime.h>
#include <math.h>

#define SEQ 2048
#define DMODEL 1024
#define QH 16
#define KVH 4
#define DH 64
#define TOPK 64
#define CCAP 256

// ---------------- scratch (__device__ globals; no allocations) ----------------
__device__ float2 g_Qff[SEQ * QH * DH];            // 16 MB roped q, float-float
__device__ float2 g_Kff[SEQ * KVH * DH];           // 4 MB  roped k, float-float
__device__ float g_Qh32[SEQ * QH * DH];            // 4 MB  hi copy for plain score GEMM
__device__ float g_Kh32[SEQ * KVH * DH];           // 1 MB
__device__ float g_V[SEQ * KVH * DH];              // 2 MB
__device__ float g_AO[SEQ * QH * DH];              // 8 MB
__device__ float g_S[QH * (size_t)SEQ * SEQ];      // 256 MB approx score slab per head
__device__ float g_cos[SEQ * 32];
__device__ float g_sin[SEQ * 32];

// ---------------- float-float primitives ----------------
// TwoSum variant (6-op compensation). PROVEN REQUIRED: Fast2Sum (round 14)
// raised rel_err 9.18e-4 -> 1.18e-3. Do not weaken this again.
__device__ __forceinline__ void ff_mac(float& h, float& l, float a, float b) {
    float p = a * b;
    float e = fmaf(a, b, -p);       // exact product error
    float s = h + p;
    float bb = s - h;
    float err = (h - (s - bb)) + (p - bb);
    h = s;
    l += err + e;
}

// ---------------- RoPE table: bit-match the reference's f32 op chain ----------------
__global__ void rope_table_kernel() {
    int idx = blockIdx.x * blockDim.x + threadIdx.x;
    if (idx >= SEQ * 32) return;
    int i = idx & 31;
    int pos = idx >> 5;
    float p32 = (float)pow(10000.0, (double)i / 32.0);
    float invf = 1.0f / p32;
    float ang = (float)pos * invf;
    const double TWO_PI = 6.283185307179586476925286766559;
    double dr = (double)ang;
    dr -= TWO_PI * floor(dr / TWO_PI + 0.5);
    g_cos[idx] = (float)cos(dr);
    g_sin[idx] = (float)sin(dr);
}

// ---------------- fused Q+K ff projection: one launch, 640 blocks ----------------
// blockIdx.x < 16 -> Wq tile into g_Qff (N=1024); else Wk tile into g_Kff (N=256).
// Per-output accumulation order identical to the separate kernels (bit-identical).
__global__ __launch_bounds__(256) void gemm_nt_ff_qk(const float* __restrict__ A,
                                                     const float* __restrict__ Wq,
                                                     const float* __restrict__ Wk) {
    __shared__ float As[16][68];
    __shared__ float Bs[16][68];
    const float* B;
    float2* C;
    int N, bnb;
    if (blockIdx.x < 16) { B = Wq; C = g_Qff; N = QH * DH; bnb = blockIdx.x; }
    else                 { B = Wk; C = g_Kff; N = KVH * DH; bnb = blockIdx.x - 16; }
    const int K = DMODEL;
    int bm = blockIdx.y * 64, bn = bnb * 64;
    int tid = threadIdx.x;
    int tx = tid & 15, ty = tid >> 4;
    float ah[4][4] = {}, al[4][4] = {};
    for (int k0 = 0; k0 < K; k0 += 16) {
#pragma unroll
        for (int t = 0; t < 4; t++) {
            int idx = tid + t * 256;
            int r = idx >> 4, kk = idx & 15;
            As[kk][r] = A[(size_t)(bm + r) * K + k0 + kk];
            Bs[kk][r] = B[(size_t)(bn + r) * K + k0 + kk];
        }
        __syncthreads();
#pragma unroll
        for (int kk = 0; kk < 16; kk++) {
            float a[4], b[4];
#pragma unroll
            for (int i = 0; i < 4; i++) a[i] = As[kk][ty * 4 + i];
#pragma unroll
            for (int j = 0; j < 4; j++) b[j] = Bs[kk][tx * 4 + j];
#pragma unroll
            for (int i = 0; i < 4; i++)
#pragma unroll
                for (int j = 0; j < 4; j++) ff_mac(ah[i][j], al[i][j], a[i], b[j]);
        }
        __syncthreads();
    }
#pragma unroll
    for (int i = 0; i < 4; i++)
#pragma unroll
        for (int j = 0; j < 4; j++) {
            float hh = ah[i][j] + al[i][j];               // renormalize
            float ll = al[i][j] - (hh - ah[i][j]);
            C[(size_t)(bm + ty * 4 + i) * N + bn + tx * 4 + j] = make_float2(hh, ll);
        }
}

// ---------------- tiled NT GEMM fp32 (V proj halves, out proj) ----------------
__global__ __launch_bounds__(256) void gemm_nt(const float* __restrict__ A,
                                               const float* __restrict__ B,
                                               float* __restrict__ C,
                                               int M, int N, int K, int m0) {
    __shared__ float As[16][68];
    __shared__ float Bs[16][68];
    int bm = blockIdx.y * 64 + m0, bn = blockIdx.x * 64;
    int tid = threadIdx.x;
    int tx = tid & 15, ty = tid >> 4;
    float acc[4][4] = {};
    for (int k0 = 0; k0 < K; k0 += 16) {
#pragma unroll
        for (int t = 0; t < 4; t++) {
            int idx = tid + t * 256;
            int r = idx >> 4, kk = idx & 15;
            As[kk][r] = A[(size_t)(bm + r) * K + k0 + kk];
            Bs[kk][r] = B[(size_t)(bn + r) * K + k0 + kk];
        }
        __syncthreads();
#pragma unroll
        for (int kk = 0; kk < 16; kk++) {
            float a[4], b[4];
#pragma unroll
            for (int i = 0; i < 4; i++) a[i] = As[kk][ty * 4 + i];
#pragma unroll
            for (int j = 0; j < 4; j++) b[j] = Bs[kk][tx * 4 + j];
#pragma unroll
            for (int i = 0; i < 4; i++)
#pragma unroll
                for (int j = 0; j < 4; j++) acc[i][j] += a[i] * b[j];
        }
        __syncthreads();
    }
#pragma unroll
    for (int i = 0; i < 4; i++)
#pragma unroll
        for (int j = 0; j < 4; j++)
            C[(size_t)(bm + ty * 4 + i) * N + bn + tx * 4 + j] = acc[i][j];
}

// ---------------- RoPE apply on float-float arrays; also writes hi copy ----------------
__global__ void rope_ff(float2* __restrict__ X, float* __restrict__ Xh, int n_heads) {
    int idx = blockIdx.x * blockDim.x + threadIdx.x;
    int total = SEQ * n_heads * 32;
    if (idx >= total) return;
    int i = idx % 32;
    int h = (idx / 32) % n_heads;
    int pos = idx / (32 * n_heads);
    double c = (double)g_cos[pos * 32 + i];
    double s = (double)g_sin[pos * 32 + i];
    size_t base = (size_t)pos * (n_heads * DH) + h * DH;
    float2* row = X + base;
    double x1 = (double)row[i].x + (double)row[i].y;
    double x2 = (double)row[i + 32].x + (double)row[i + 32].y;
    double r1 = x1 * c - x2 * s;
    double r2 = x2 * c + x1 * s;
    float h1 = (float)r1, h2 = (float)r2;
    row[i]      = make_float2(h1, (float)(r1 - (double)h1));
    row[i + 32] = make_float2(h2, (float)(r2 - (double)h2));
    Xh[base + i] = h1;
    Xh[base + i + 32] = h2;
}

// monotone float->uint map (order-preserving)
__device__ __forceinline__ unsigned fmap(float f) {
    unsigned u = __float_as_uint(f);
    return (u & 0x80000000u) ? ~u : (u | 0x80000000u);
}
// inverse of fmap
__device__ __forceinline__ float funmap(unsigned u) {
    return __uint_as_float((u & 0x80000000u) ? (u & 0x7FFFFFFFu) : ~u);
}

// ---------------- approx score GEMM (plain fp32 on hi parts), 16 heads ----------------
__global__ __launch_bounds__(256) void score_plain16() {
    __shared__ float Qs[64][65];
    __shared__ float Ks[64][65];
    int tid = threadIdx.x;
    int h = blockIdx.y;
    int t = blockIdx.x;
    int bi = (int)((sqrtf(8.0f * (float)t + 1.0f) - 1.0f) * 0.5f);
    while ((bi + 1) * (bi + 2) / 2 <= t) bi++;
    while (bi * (bi + 1) / 2 > t) bi--;
    int bj = t - bi * (bi + 1) / 2;
    int qi0 = bi * 64, j0 = bj * 64;
    int kvh = h >> 2;
    float* Sh = g_S + (size_t)h * SEQ * SEQ;
    const float* Qp = g_Qh32 + (size_t)qi0 * (QH * DH) + h * DH;
    const float* Kp = g_Kh32 + (size_t)j0 * (KVH * DH) + kvh * DH;

#pragma unroll
    for (int p = 0; p < 16; p++) {
        int idx = tid + p * 256;
        int d = idx & 63, r = idx >> 6;
        Qs[d][r] = Qp[(size_t)r * (QH * DH) + d];
        Ks[d][r] = Kp[(size_t)r * (KVH * DH) + d];
    }
    __syncthreads();

    int tx = tid & 15, ty = tid >> 4;
    float acc[4][4] = {};
#pragma unroll 8
    for (int kk = 0; kk < 64; kk++) {
        float a[4], b[4];
#pragma unroll
        for (int i = 0; i < 4; i++) a[i] = Qs[kk][ty + 16 * i];
#pragma unroll
        for (int j = 0; j < 4; j++) b[j] = Ks[kk][tx + 16 * j];
#pragma unroll
        for (int i = 0; i < 4; i++)
#pragma unroll
            for (int j = 0; j < 4; j++) acc[i][j] += a[i] * b[j];
    }
#pragma unroll
    for (int i = 0; i < 4; i++) {
        int qi = qi0 + ty + 16 * i;
#pragma unroll
        for (int j = 0; j < 4; j++) {
            int jj = j0 + tx + 16 * j;
            if (jj <= qi)
                Sh[(size_t)qi * SEQ + jj] = acc[i][j] * 0.125f;
        }
    }
}

// ---------------- attention: parallel radix cutoff -> exact recompute of candidates ----------------
__global__ __launch_bounds__(256) void attn16() {
    __shared__ float sc[SEQ];
    __shared__ int hist[256];
    __shared__ int cidx[CCAP];
    __shared__ float cval[CCAP];
    __shared__ float cwgt[CCAP];
    __shared__ float2 q2s[DH];
    __shared__ float fred[8];
    __shared__ int s_wc[8];
    __shared__ float s_smax, s_den;
    __shared__ int s_b, s_k, s_cnt;
    __shared__ float4 red4[16][16];

    int tid = threadIdx.x, lane = tid & 31, wid = tid >> 5;
    int qi = blockIdx.x;
    int h = blockIdx.y;
    int kvh = h >> 2;
    int len = qi + 1;

    if (tid < DH) q2s[tid] = g_Qff[(size_t)qi * (QH * DH) + h * DH + tid];
    hist[tid] = 0;
    __syncthreads();

    // ---- fused row load + level-1 histogram (bits [31:24]) ----
    const float* Srow = g_S + (size_t)h * SEQ * SEQ + (size_t)qi * SEQ;
    for (int j = tid; j < len; j += 256) {
        float v = Srow[j];
        sc[j] = v;
        atomicAdd(&hist[fmap(v) >> 24], 1);
    }
    __syncthreads();

    float vlo = -INFINITY;
    if (len > TOPK) {
        // ---- level-1: parallel suffix scan, find cutoff bin ----
        {
            int rs = 255 - tid;
            int v1 = hist[rs];
            int x = v1;
#pragma unroll
            for (int o = 1; o < 32; o <<= 1) {
                int y = __shfl_up_sync(0xffffffffu, x, o);
                if (lane >= o) x += y;
            }
            if (lane == 31) s_wc[wid] = x;
            __syncthreads();
            int wo = 0;
            for (int w = 0; w < wid; w++) wo += s_wc[w];
            int incl = x + wo, excl = incl - v1;
            if (incl >= TOPK && excl < TOPK) { s_b = rs; s_k = TOPK - excl; }
            __syncthreads();
        }
        int b1 = s_b, k1 = s_k;

        // ---- level-2 histogram (bits [23:16]) within bin b1 ----
        hist[tid] = 0;
        __syncthreads();
        for (int j = tid; j < len; j += 256) {
            unsigned u = fmap(sc[j]);
            if ((int)(u >> 24) == b1) atomicAdd(&hist[(u >> 16) & 0xFF], 1);
        }
        __syncthreads();
        {
            int rs = 255 - tid;
            int v1 = hist[rs];
            int x = v1;
#pragma unroll
            for (int o = 1; o < 32; o <<= 1) {
                int y = __shfl_up_sync(0xffffffffu, x, o);
                if (lane >= o) x += y;
            }
            if (lane == 31) s_wc[wid] = x;
            __syncthreads();
            int wo = 0;
            for (int w = 0; w < wid; w++) wo += s_wc[w];
            int incl = x + wo, excl = incl - v1;
            if (incl >= k1 && excl < k1) s_b = rs;
            __syncthreads();
        }
        unsigned floorx = ((unsigned)b1 << 24) | ((unsigned)s_b << 16);
        vlo = funmap(floorx);
    }

    // ---- deterministic compaction: per-thread collect + block exclusive scan ----
    int cnt = 0;
    for (int attempt = 0; attempt < 2; attempt++) {
        float cutoff = (len > TOPK) ? (attempt == 0 ? vlo - 1e-4f : vlo) : -INFINITY;
        int lc = 0;
        int lcs[8];
        for (int c = 0; c * 256 + tid < len; c++) {
            int j = c * 256 + tid;
            if (sc[j] >= cutoff) lcs[lc++] = j;
        }
        int x = lc;
#pragma unroll
        for (int o = 1; o < 32; o <<= 1) {
            int y = __shfl_up_sync(0xffffffffu, x, o);
            if (lane >= o) x += y;
        }
        if (lane == 31) s_wc[wid] = x;
        __syncthreads();
        int wo = 0;
        for (int w = 0; w < wid; w++) wo += s_wc[w];
        int off = wo + x - lc;
        if (tid == 0) {
            int t = 0;
            for (int w = 0; w < 8; w++) t += s_wc[w];
            s_cnt = t;
        }
        for (int i = 0; i < lc; i++) {
            int pos = off + i;
            if (pos < CCAP) cidx[pos] = lcs[i];
        }
        __syncthreads();
        cnt = s_cnt < CCAP ? s_cnt : CCAP;
        if (s_cnt <= CCAP || len <= TOPK) break;
        __syncthreads();
    }

    // ---- exact ff recompute for candidates (warp per candidate) ----
    for (int t = wid; t < cnt; t += 8) {
        int j = cidx[t];
        const float2* kr = g_Kff + (size_t)j * (KVH * DH) + kvh * DH;
        float2 k1v = kr[lane], k2v = kr[lane + 32];
        float2 qa = q2s[lane], qb = q2s[lane + 32];
        float sh = 0.f, sl = 0.f;
        ff_mac(sh, sl, qa.x, k1v.x);
        sl += qa.x * k1v.y + qa.y * k1v.x;
        ff_mac(sh, sl, qb.x, k2v.x);
        sl += qb.x * k2v.y + qb.y * k2v.x;
#pragma unroll
        for (int o = 16; o; o >>= 1) {
            float oh = __shfl_xor_sync(0xffffffffu, sh, o);
            float ol = __shfl_xor_sync(0xffffffffu, sl, o);
            float s = sh + oh;
            float bb = s - sh;
            float err = (sh - (s - bb)) + (oh - bb);
            sh = s;
            sl += ol + err;
        }
        if (lane == 0) cval[t] = (sh + sl) * 0.125f;
    }
    __syncthreads();

    // ---- smax over candidate exacts (global max is always a candidate) ----
    {
        float lm = (tid < cnt) ? cval[tid] : -INFINITY;
#pragma unroll
        for (int o = 16; o; o >>= 1) lm = fmaxf(lm, __shfl_xor_sync(0xffffffffu, lm, o));
        if (lane == 0) fred[wid] = lm;
        __syncthreads();
        if (tid == 0) {
            float mm = fred[0];
            for (int w = 1; w < 8; w++) mm = fmaxf(mm, fred[w]);
            s_smax = mm;
        }
        __syncthreads();
    }
    float smax = s_smax;

    // ---- exact 64th-largest among candidates via bit search (deterministic) ----
    unsigned myu = (tid < cnt) ? fmap(cval[tid]) : 0u;
    unsigned thru = 0;
    if (len > TOPK) {
        unsigned prefix = 0;
#pragma unroll
        for (int b = 31; b >= 0; b--) {
            unsigned cand = prefix | (1u << b);
            int c = __syncthreads_count((tid < cnt) && (myu >= cand));
            if (c >= TOPK) prefix = cand;
        }
        thru = prefix;  // exact u of the 64th-largest true score; keep u >= thru (ties kept)
    }

    // ---- weights ----
    {
        float w = 0.f;
        if (tid < cnt && myu >= thru) w = expf(cval[tid] - smax);
        cwgt[tid] = w;
    }
    __syncthreads();

    // ---- denominator (fixed order) ----
    {
        float part = cwgt[tid];
#pragma unroll
        for (int o = 16; o; o >>= 1) part += __shfl_xor_sync(0xffffffffu, part, o);
        if (lane == 0) fred[wid] = part;
        __syncthreads();
        if (tid == 0) {
            float d = 0.f;
            for (int w = 0; w < 8; w++) d += fred[w];
            s_den = d;
        }
        __syncthreads();
    }
    float inv = 1.f / s_den;

    // ---- AV over candidate list: 16 groups x 16 float4-dims ----
    {
        int g = tid >> 4, d4 = tid & 15;
        float4 a = make_float4(0.f, 0.f, 0.f, 0.f);
        for (int t = g; t < cnt; t += 16) {
            float wv = cwgt[t];
            if (wv != 0.f) {
                float4 vv = *((const float4*)(g_V + (size_t)cidx[t] * (KVH * DH) + kvh * DH) + d4);
                a.x += wv * vv.x; a.y += wv * vv.y;
                a.z += wv * vv.z; a.w += wv * vv.w;
            }
        }
        red4[g][d4] = a;
    }
    __syncthreads();
    if (tid < 16) {
        float4 a = make_float4(0.f, 0.f, 0.f, 0.f);
        for (int g = 0; g < 16; g++) {
            float4 v = red4[g][tid];
            a.x += v.x; a.y += v.y; a.z += v.z; a.w += v.w;
        }
        a.x *= inv; a.y *= inv; a.z *= inv; a.w *= inv;
        *((float4*)(g_AO + (size_t)qi * (QH * DH) + h * DH) + tid) = a;
    }
}

// ---------------- launch ----------------
extern "C" void kernel_launch(void* const* d_in, const int* in_sizes, int n_in,
                              void* d_out, int out_size) {
    (void)out_size;
    int ixv = -1, big[2] = {-1, -1}, sml[2] = {-1, -1};
    int nb = 0, ns = 0;
    for (int i = 0; i < n_in; i++) {
        if (in_sizes[i] == SEQ * DMODEL && ixv < 0) ixv = i;
        else if (in_sizes[i] == QH * DH * DMODEL && nb < 2) big[nb++] = i;
        else if (in_sizes[i] == KVH * DH * DMODEL && ns < 2) sml[ns++] = i;
    }
    if (ixv < 0 || nb < 2 || ns < 2) {
        ixv = 0; big[0] = 1; big[1] = 4; sml[0] = 2; sml[1] = 3;
    }
    const float* x  = (const float*)d_in[ixv];
    const float* Wq = (const float*)d_in[big[0]];
    const float* Wo = (const float*)d_in[big[1]];
    const float* Wk = (const float*)d_in[sml[0]];
    const float* Wv = (const float*)d_in[sml[1]];
    float* out = (float*)d_out;

    float2 *Qff, *Kff;
    float *V, *AO, *Qh32, *Kh32;
    cudaGetSymbolAddress((void**)&Qff, g_Qff);
    cudaGetSymbolAddress((void**)&Kff, g_Kff);
    cudaGetSymbolAddress((void**)&V, g_V);
    cudaGetSymbolAddress((void**)&AO, g_AO);
    cudaGetSymbolAddress((void**)&Qh32, g_Qh32);
    cudaGetSymbolAddress((void**)&Kh32, g_Kh32);

    // launch order puts the fused QK ff GEMM in the ncu capture slot (#4).
    rope_table_kernel<<<(SEQ * 32 + 255) / 256, 256>>>();
    gemm_nt<<<dim3((KVH * DH) / 64, SEQ / 128), 256>>>(x, Wv, V, SEQ, KVH * DH, DMODEL, 0);
    gemm_nt<<<dim3((KVH * DH) / 64, SEQ / 128), 256>>>(x, Wv, V, SEQ, KVH * DH, DMODEL, SEQ / 2);

    gemm_nt_ff_qk<<<dim3(20, SEQ / 64), 256>>>(x, Wq, Wk);

    rope_ff<<<(SEQ * QH * 32) / 256, 256>>>(Qff, Qh32, QH);
    rope_ff<<<(SEQ * KVH * 32) / 256, 256>>>(Kff, Kh32, KVH);

    const int NT = (SEQ / 64) * (SEQ / 64 + 1) / 2;  // 528 triangular tiles
    score_plain16<<<dim3(NT, QH), 256>>>();
    attn16<<<dim3(SEQ, QH), 256>>>();

    gemm_nt<<<dim3(DMODEL / 64, SEQ / 64), 256>>>(AO, Wo, out, SEQ, DMODEL, QH * DH, 0);
}

// round 17
// speedup vs baseline: 1.6375x; 1.6063x over previous
#include <cuda_runtime.h>
#include <math.h>

#define SEQ 2048
#define DMODEL 1024
#define QH 16
#define KVH 4
#define DH 64
#define TOPK 64
#define CCAP 256

// ---------------- scratch (__device__ globals; no allocations) ----------------
__device__ float2 g_Qff[SEQ * QH * DH];            // 16 MB roped q, float-float
__device__ float2 g_Kff[SEQ * KVH * DH];           // 4 MB  roped k, float-float
__device__ float g_Qh32[SEQ * QH * DH];            // 4 MB  hi copy for plain score GEMM
__device__ float g_Kh32[SEQ * KVH * DH];           // 1 MB
__device__ float g_V[SEQ * KVH * DH];              // 2 MB
__device__ float g_AO[SEQ * QH * DH];              // 8 MB
__device__ float g_S[QH * (size_t)SEQ * SEQ];      // 256 MB approx score slab per head
__device__ float g_cos[SEQ * 32];
__device__ float g_sin[SEQ * 32];

// ---------------- float-float primitives ----------------
// TwoSum variant (6-op compensation). PROVEN REQUIRED for per-MAC paths:
// Fast2Sum (round 14) raised rel_err 9.18e-4 -> 1.18e-3. Do not weaken.
__device__ __forceinline__ void ff_mac(float& h, float& l, float a, float b) {
    float p = a * b;
    float e = fmaf(a, b, -p);       // exact product error
    float s = h + p;
    float bb = s - h;
    float err = (h - (s - bb)) + (p - bb);
    h = s;
    l += err + e;
}

// Full TwoSum merge of a block partial t into (h,l). Exact for ALL magnitude
// orderings (this is NOT Fast2Sum). Used by the blocked ff GEMM: each 16-wide
// k-tile is accumulated in plain fp32 from zero (block partials stay tiny, so
// their rounding is ~1e-9-1e-8 absolute), then folded exactly.
__device__ __forceinline__ void ff_merge(float& h, float& l, float t) {
    float s = h + t;
    float bb = s - h;
    float err = (h - (s - bb)) + (t - bb);
    h = s;
    l += err;
}

// ---------------- RoPE table: bit-match the reference's f32 op chain ----------------
__global__ void rope_table_kernel() {
    int idx = blockIdx.x * blockDim.x + threadIdx.x;
    if (idx >= SEQ * 32) return;
    int i = idx & 31;
    int pos = idx >> 5;
    float p32 = (float)pow(10000.0, (double)i / 32.0);
    float invf = 1.0f / p32;
    float ang = (float)pos * invf;
    const double TWO_PI = 6.283185307179586476925286766559;
    double dr = (double)ang;
    dr -= TWO_PI * floor(dr / TWO_PI + 0.5);
    g_cos[idx] = (float)cos(dr);
    g_sin[idx] = (float)sin(dr);
}

// ---------------- fused Q+K ff projection, blocked compensation ----------------
// blockIdx.x < 16 -> Wq tile into g_Qff (N=1024); else Wk tile into g_Kff (N=256).
// Inner: 16-wide k-tile accumulated in plain fp32 (from zero), one TwoSum merge
// per tile into the ff accumulator. ~1.44 ops/MAC vs 10 for per-MAC TwoSum.
__global__ __launch_bounds__(256) void gemm_nt_ff_qk(const float* __restrict__ A,
                                                     const float* __restrict__ Wq,
                                                     const float* __restrict__ Wk) {
    __shared__ float As[16][68];
    __shared__ float Bs[16][68];
    const float* B;
    float2* C;
    int N, bnb;
    if (blockIdx.x < 16) { B = Wq; C = g_Qff; N = QH * DH; bnb = blockIdx.x; }
    else                 { B = Wk; C = g_Kff; N = KVH * DH; bnb = blockIdx.x - 16; }
    const int K = DMODEL;
    int bm = blockIdx.y * 64, bn = bnb * 64;
    int tid = threadIdx.x;
    int tx = tid & 15, ty = tid >> 4;
    float ah[4][4] = {}, al[4][4] = {};
    for (int k0 = 0; k0 < K; k0 += 16) {
#pragma unroll
        for (int t = 0; t < 4; t++) {
            int idx = tid + t * 256;
            int r = idx >> 4, kk = idx & 15;
            As[kk][r] = A[(size_t)(bm + r) * K + k0 + kk];
            Bs[kk][r] = B[(size_t)(bn + r) * K + k0 + kk];
        }
        __syncthreads();
        float t16[4][4];
#pragma unroll
        for (int kk = 0; kk < 16; kk++) {
            float a[4], b[4];
#pragma unroll
            for (int i = 0; i < 4; i++) a[i] = As[kk][ty * 4 + i];
#pragma unroll
            for (int j = 0; j < 4; j++) b[j] = Bs[kk][tx * 4 + j];
            if (kk == 0) {
#pragma unroll
                for (int i = 0; i < 4; i++)
#pragma unroll
                    for (int j = 0; j < 4; j++) t16[i][j] = a[i] * b[j];
            } else {
#pragma unroll
                for (int i = 0; i < 4; i++)
#pragma unroll
                    for (int j = 0; j < 4; j++) t16[i][j] = fmaf(a[i], b[j], t16[i][j]);
            }
        }
#pragma unroll
        for (int i = 0; i < 4; i++)
#pragma unroll
            for (int j = 0; j < 4; j++) ff_merge(ah[i][j], al[i][j], t16[i][j]);
        __syncthreads();
    }
#pragma unroll
    for (int i = 0; i < 4; i++)
#pragma unroll
        for (int j = 0; j < 4; j++) {
            float hh = ah[i][j] + al[i][j];               // renormalize
            float ll = al[i][j] - (hh - ah[i][j]);
            C[(size_t)(bm + ty * 4 + i) * N + bn + tx * 4 + j] = make_float2(hh, ll);
        }
}

// ---------------- tiled NT GEMM fp32 (V proj, out proj) ----------------
__global__ __launch_bounds__(256) void gemm_nt(const float* __restrict__ A,
                                               const float* __restrict__ B,
                                               float* __restrict__ C,
                                               int M, int N, int K) {
    __shared__ float As[16][68];
    __shared__ float Bs[16][68];
    int bm = blockIdx.y * 64, bn = blockIdx.x * 64;
    int tid = threadIdx.x;
    int tx = tid & 15, ty = tid >> 4;
    float acc[4][4] = {};
    for (int k0 = 0; k0 < K; k0 += 16) {
#pragma unroll
        for (int t = 0; t < 4; t++) {
            int idx = tid + t * 256;
            int r = idx >> 4, kk = idx & 15;
            As[kk][r] = A[(size_t)(bm + r) * K + k0 + kk];
            Bs[kk][r] = B[(size_t)(bn + r) * K + k0 + kk];
        }
        __syncthreads();
#pragma unroll
        for (int kk = 0; kk < 16; kk++) {
            float a[4], b[4];
#pragma unroll
            for (int i = 0; i < 4; i++) a[i] = As[kk][ty * 4 + i];
#pragma unroll
            for (int j = 0; j < 4; j++) b[j] = Bs[kk][tx * 4 + j];
#pragma unroll
            for (int i = 0; i < 4; i++)
#pragma unroll
                for (int j = 0; j < 4; j++) acc[i][j] += a[i] * b[j];
        }
        __syncthreads();
    }
#pragma unroll
    for (int i = 0; i < 4; i++)
#pragma unroll
        for (int j = 0; j < 4; j++)
            C[(size_t)(bm + ty * 4 + i) * N + bn + tx * 4 + j] = acc[i][j];
}

// ---------------- RoPE apply on float-float arrays; also writes hi copy ----------------
__global__ void rope_ff(float2* __restrict__ X, float* __restrict__ Xh, int n_heads) {
    int idx = blockIdx.x * blockDim.x + threadIdx.x;
    int total = SEQ * n_heads * 32;
    if (idx >= total) return;
    int i = idx % 32;
    int h = (idx / 32) % n_heads;
    int pos = idx / (32 * n_heads);
    double c = (double)g_cos[pos * 32 + i];
    double s = (double)g_sin[pos * 32 + i];
    size_t base = (size_t)pos * (n_heads * DH) + h * DH;
    float2* row = X + base;
    double x1 = (double)row[i].x + (double)row[i].y;
    double x2 = (double)row[i + 32].x + (double)row[i + 32].y;
    double r1 = x1 * c - x2 * s;
    double r2 = x2 * c + x1 * s;
    float h1 = (float)r1, h2 = (float)r2;
    row[i]      = make_float2(h1, (float)(r1 - (double)h1));
    row[i + 32] = make_float2(h2, (float)(r2 - (double)h2));
    Xh[base + i] = h1;
    Xh[base + i + 32] = h2;
}

// monotone float->uint map (order-preserving)
__device__ __forceinline__ unsigned fmap(float f) {
    unsigned u = __float_as_uint(f);
    return (u & 0x80000000u) ? ~u : (u | 0x80000000u);
}
// inverse of fmap
__device__ __forceinline__ float funmap(unsigned u) {
    return __uint_as_float((u & 0x80000000u) ? (u & 0x7FFFFFFFu) : ~u);
}

// ---------------- approx score GEMM (plain fp32 on hi parts), 16 heads ----------------
__global__ __launch_bounds__(256) void score_plain16() {
    __shared__ float Qs[64][65];
    __shared__ float Ks[64][65];
    int tid = threadIdx.x;
    int h = blockIdx.y;
    int t = blockIdx.x;
    int bi = (int)((sqrtf(8.0f * (float)t + 1.0f) - 1.0f) * 0.5f);
    while ((bi + 1) * (bi + 2) / 2 <= t) bi++;
    while (bi * (bi + 1) / 2 > t) bi--;
    int bj = t - bi * (bi + 1) / 2;
    int qi0 = bi * 64, j0 = bj * 64;
    int kvh = h >> 2;
    float* Sh = g_S + (size_t)h * SEQ * SEQ;
    const float* Qp = g_Qh32 + (size_t)qi0 * (QH * DH) + h * DH;
    const float* Kp = g_Kh32 + (size_t)j0 * (KVH * DH) + kvh * DH;

#pragma unroll
    for (int p = 0; p < 16; p++) {
        int idx = tid + p * 256;
        int d = idx & 63, r = idx >> 6;
        Qs[d][r] = Qp[(size_t)r * (QH * DH) + d];
        Ks[d][r] = Kp[(size_t)r * (KVH * DH) + d];
    }
    __syncthreads();

    int tx = tid & 15, ty = tid >> 4;
    float acc[4][4] = {};
#pragma unroll 8
    for (int kk = 0; kk < 64; kk++) {
        float a[4], b[4];
#pragma unroll
        for (int i = 0; i < 4; i++) a[i] = Qs[kk][ty + 16 * i];
#pragma unroll
        for (int j = 0; j < 4; j++) b[j] = Ks[kk][tx + 16 * j];
#pragma unroll
        for (int i = 0; i < 4; i++)
#pragma unroll
            for (int j = 0; j < 4; j++) acc[i][j] += a[i] * b[j];
    }
#pragma unroll
    for (int i = 0; i < 4; i++) {
        int qi = qi0 + ty + 16 * i;
#pragma unroll
        for (int j = 0; j < 4; j++) {
            int jj = j0 + tx + 16 * j;
            if (jj <= qi)
                Sh[(size_t)qi * SEQ + jj] = acc[i][j] * 0.125f;
        }
    }
}

// ---------------- attention: parallel radix cutoff -> exact recompute of candidates ----------------
__global__ __launch_bounds__(256) void attn16() {
    __shared__ float sc[SEQ];
    __shared__ int hist[256];
    __shared__ int cidx[CCAP];
    __shared__ float cval[CCAP];
    __shared__ float cwgt[CCAP];
    __shared__ float2 q2s[DH];
    __shared__ float fred[8];
    __shared__ int s_wc[8];
    __shared__ float s_smax, s_den;
    __shared__ int s_b, s_k, s_cnt;
    __shared__ float4 red4[16][16];

    int tid = threadIdx.x, lane = tid & 31, wid = tid >> 5;
    int qi = blockIdx.x;
    int h = blockIdx.y;
    int kvh = h >> 2;
    int len = qi + 1;

    if (tid < DH) q2s[tid] = g_Qff[(size_t)qi * (QH * DH) + h * DH + tid];
    hist[tid] = 0;
    __syncthreads();

    // ---- fused row load + level-1 histogram (bits [31:24]) ----
    const float* Srow = g_S + (size_t)h * SEQ * SEQ + (size_t)qi * SEQ;
    for (int j = tid; j < len; j += 256) {
        float v = Srow[j];
        sc[j] = v;
        atomicAdd(&hist[fmap(v) >> 24], 1);
    }
    __syncthreads();

    float vlo = -INFINITY;
    if (len > TOPK) {
        // ---- level-1: parallel suffix scan, find cutoff bin ----
        {
            int rs = 255 - tid;
            int v1 = hist[rs];
            int x = v1;
#pragma unroll
            for (int o = 1; o < 32; o <<= 1) {
                int y = __shfl_up_sync(0xffffffffu, x, o);
                if (lane >= o) x += y;
            }
            if (lane == 31) s_wc[wid] = x;
            __syncthreads();
            int wo = 0;
            for (int w = 0; w < wid; w++) wo += s_wc[w];
            int incl = x + wo, excl = incl - v1;
            if (incl >= TOPK && excl < TOPK) { s_b = rs; s_k = TOPK - excl; }
            __syncthreads();
        }
        int b1 = s_b, k1 = s_k;

        // ---- level-2 histogram (bits [23:16]) within bin b1 ----
        hist[tid] = 0;
        __syncthreads();
        for (int j = tid; j < len; j += 256) {
            unsigned u = fmap(sc[j]);
            if ((int)(u >> 24) == b1) atomicAdd(&hist[(u >> 16) & 0xFF], 1);
        }
        __syncthreads();
        {
            int rs = 255 - tid;
            int v1 = hist[rs];
            int x = v1;
#pragma unroll
            for (int o = 1; o < 32; o <<= 1) {
                int y = __shfl_up_sync(0xffffffffu, x, o);
                if (lane >= o) x += y;
            }
            if (lane == 31) s_wc[wid] = x;
            __syncthreads();
            int wo = 0;
            for (int w = 0; w < wid; w++) wo += s_wc[w];
            int incl = x + wo, excl = incl - v1;
            if (incl >= k1 && excl < k1) s_b = rs;
            __syncthreads();
        }
        unsigned floorx = ((unsigned)b1 << 24) | ((unsigned)s_b << 16);
        vlo = funmap(floorx);
    }

    // ---- deterministic compaction: per-thread collect + block exclusive scan ----
    int cnt = 0;
    for (int attempt = 0; attempt < 2; attempt++) {
        float cutoff = (len > TOPK) ? (attempt == 0 ? vlo - 1e-4f : vlo) : -INFINITY;
        int lc = 0;
        int lcs[8];
        for (int c = 0; c * 256 + tid < len; c++) {
            int j = c * 256 + tid;
            if (sc[j] >= cutoff) lcs[lc++] = j;
        }
        int x = lc;
#pragma unroll
        for (int o = 1; o < 32; o <<= 1) {
            int y = __shfl_up_sync(0xffffffffu, x, o);
            if (lane >= o) x += y;
        }
        if (lane == 31) s_wc[wid] = x;
        __syncthreads();
        int wo = 0;
        for (int w = 0; w < wid; w++) wo += s_wc[w];
        int off = wo + x - lc;
        if (tid == 0) {
            int t = 0;
            for (int w = 0; w < 8; w++) t += s_wc[w];
            s_cnt = t;
        }
        for (int i = 0; i < lc; i++) {
            int pos = off + i;
            if (pos < CCAP) cidx[pos] = lcs[i];
        }
        __syncthreads();
        cnt = s_cnt < CCAP ? s_cnt : CCAP;
        if (s_cnt <= CCAP || len <= TOPK) break;
        __syncthreads();
    }

    // ---- exact ff recompute for candidates (warp per candidate) ----
    for (int t = wid; t < cnt; t += 8) {
        int j = cidx[t];
        const float2* kr = g_Kff + (size_t)j * (KVH * DH) + kvh * DH;
        float2 k1v = kr[lane], k2v = kr[lane + 32];
        float2 qa = q2s[lane], qb = q2s[lane + 32];
        float sh = 0.f, sl = 0.f;
        ff_mac(sh, sl, qa.x, k1v.x);
        sl += qa.x * k1v.y + qa.y * k1v.x;
        ff_mac(sh, sl, qb.x, k2v.x);
        sl += qb.x * k2v.y + qb.y * k2v.x;
#pragma unroll
        for (int o = 16; o; o >>= 1) {
            float oh = __shfl_xor_sync(0xffffffffu, sh, o);
            float ol = __shfl_xor_sync(0xffffffffu, sl, o);
            float s = sh + oh;
            float bb = s - sh;
            float err = (sh - (s - bb)) + (oh - bb);
            sh = s;
            sl += ol + err;
        }
        if (lane == 0) cval[t] = (sh + sl) * 0.125f;
    }
    __syncthreads();

    // ---- smax over candidate exacts (global max is always a candidate) ----
    {
        float lm = (tid < cnt) ? cval[tid] : -INFINITY;
#pragma unroll
        for (int o = 16; o; o >>= 1) lm = fmaxf(lm, __shfl_xor_sync(0xffffffffu, lm, o));
        if (lane == 0) fred[wid] = lm;
        __syncthreads();
        if (tid == 0) {
            float mm = fred[0];
            for (int w = 1; w < 8; w++) mm = fmaxf(mm, fred[w]);
            s_smax = mm;
        }
        __syncthreads();
    }
    float smax = s_smax;

    // ---- exact 64th-largest among candidates via bit search (deterministic) ----
    unsigned myu = (tid < cnt) ? fmap(cval[tid]) : 0u;
    unsigned thru = 0;
    if (len > TOPK) {
        unsigned prefix = 0;
#pragma unroll
        for (int b = 31; b >= 0; b--) {
            unsigned cand = prefix | (1u << b);
            int c = __syncthreads_count((tid < cnt) && (myu >= cand));
            if (c >= TOPK) prefix = cand;
        }
        thru = prefix;  // exact u of the 64th-largest true score; keep u >= thru (ties kept)
    }

    // ---- weights ----
    {
        float w = 0.f;
        if (tid < cnt && myu >= thru) w = expf(cval[tid] - smax);
        cwgt[tid] = w;
    }
    __syncthreads();

    // ---- denominator (fixed order) ----
    {
        float part = cwgt[tid];
#pragma unroll
        for (int o = 16; o; o >>= 1) part += __shfl_xor_sync(0xffffffffu, part, o);
        if (lane == 0) fred[wid] = part;
        __syncthreads();
        if (tid == 0) {
            float d = 0.f;
            for (int w = 0; w < 8; w++) d += fred[w];
            s_den = d;
        }
        __syncthreads();
    }
    float inv = 1.f / s_den;

    // ---- AV over candidate list: 16 groups x 16 float4-dims ----
    {
        int g = tid >> 4, d4 = tid & 15;
        float4 a = make_float4(0.f, 0.f, 0.f, 0.f);
        for (int t = g; t < cnt; t += 16) {
            float wv = cwgt[t];
            if (wv != 0.f) {
                float4 vv = *((const float4*)(g_V + (size_t)cidx[t] * (KVH * DH) + kvh * DH) + d4);
                a.x += wv * vv.x; a.y += wv * vv.y;
                a.z += wv * vv.z; a.w += wv * vv.w;
            }
        }
        red4[g][d4] = a;
    }
    __syncthreads();
    if (tid < 16) {
        float4 a = make_float4(0.f, 0.f, 0.f, 0.f);
        for (int g = 0; g < 16; g++) {
            float4 v = red4[g][tid];
            a.x += v.x; a.y += v.y; a.z += v.z; a.w += v.w;
        }
        a.x *= inv; a.y *= inv; a.z *= inv; a.w *= inv;
        *((float4*)(g_AO + (size_t)qi * (QH * DH) + h * DH) + tid) = a;
    }
}

// ---------------- launch ----------------
extern "C" void kernel_launch(void* const* d_in, const int* in_sizes, int n_in,
                              void* d_out, int out_size) {
    (void)out_size;
    int ixv = -1, big[2] = {-1, -1}, sml[2] = {-1, -1};
    int nb = 0, ns = 0;
    for (int i = 0; i < n_in; i++) {
        if (in_sizes[i] == SEQ * DMODEL && ixv < 0) ixv = i;
        else if (in_sizes[i] == QH * DH * DMODEL && nb < 2) big[nb++] = i;
        else if (in_sizes[i] == KVH * DH * DMODEL && ns < 2) sml[ns++] = i;
    }
    if (ixv < 0 || nb < 2 || ns < 2) {
        ixv = 0; big[0] = 1; big[1] = 4; sml[0] = 2; sml[1] = 3;
    }
    const float* x  = (const float*)d_in[ixv];
    const float* Wq = (const float*)d_in[big[0]];
    const float* Wo = (const float*)d_in[big[1]];
    const float* Wk = (const float*)d_in[sml[0]];
    const float* Wv = (const float*)d_in[sml[1]];
    float* out = (float*)d_out;

    float2 *Qff, *Kff;
    float *V, *AO, *Qh32, *Kh32;
    cudaGetSymbolAddress((void**)&Qff, g_Qff);
    cudaGetSymbolAddress((void**)&Kff, g_Kff);
    cudaGetSymbolAddress((void**)&V, g_V);
    cudaGetSymbolAddress((void**)&AO, g_AO);
    cudaGetSymbolAddress((void**)&Qh32, g_Qh32);
    cudaGetSymbolAddress((void**)&Kh32, g_Kh32);

    // rope_table launched twice (idempotent) so the fused QK ff GEMM sits in
    // the ncu capture slot (#4) for direct measurement of the blocked-ff win.
    rope_table_kernel<<<(SEQ * 32 + 255) / 256, 256>>>();
    gemm_nt<<<dim3((KVH * DH) / 64, SEQ / 64), 256>>>(x, Wv, V, SEQ, KVH * DH, DMODEL);
    rope_table_kernel<<<(SEQ * 32 + 255) / 256, 256>>>();

    gemm_nt_ff_qk<<<dim3(20, SEQ / 64), 256>>>(x, Wq, Wk);

    rope_ff<<<(SEQ * QH * 32) / 256, 256>>>(Qff, Qh32, QH);
    rope_ff<<<(SEQ * KVH * 32) / 256, 256>>>(Kff, Kh32, KVH);

    const int NT = (SEQ / 64) * (SEQ / 64 + 1) / 2;  // 528 triangular tiles
    score_plain16<<<dim3(NT, QH), 256>>>();
    attn16<<<dim3(SEQ, QH), 256>>>();

    gemm_nt<<<dim3(DMODEL / 64, SEQ / 64), 256>>>(AO, Wo, out, SEQ, DMODEL, QH * DH);
}